// round 10
// baseline (speedup 1.0000x reference)
#include <cuda_runtime.h>
#include <cstdint>

// VQ nearest-codebook, fp32-exact, Blackwell dual-FP32 (fma.rn.f32x2).
// Orientation: POINTS distributed across lanes (4/lane), CODEWORD PAIRS
// broadcast (warp w owns codewords 16w..16w+15 of each 128-cw chunk).
// Block = 128 points (2 (b,h) rows), 256 threads, grid 512.

#define DD 64
#define KTOT 1024
#define TK 128          // codewords per chunk
#define PTS 128         // points per block
#define NTHREADS 256
#define NCHUNK (KTOT / TK)

#define PSROW 132       // 128 points + 4 pad (floats)
#define CSROW 132       // 128 codewords + 4 pad
#define SMEM_FLOATS (DD * PSROW + 2 * DD * CSROW)   // 25344 floats = 101376 B

__device__ float g_cbT[DD * KTOT];   // codebook transposed [d][k]
__device__ float g_cnorm[KTOT];

#define FMA2(d, a, b) \
    asm("fma.rn.f32x2 %0, %1, %2, %0;" : "+l"(d) : "l"(a), "l"(b))
#define UNPACK2(u0, u1, v) \
    asm("mov.b64 {%0, %1}, %2;" : "=r"(u0), "=r"(u1) : "l"(v))
#define DUP2(d, s) \
    asm("mov.b64 %0, {%1, %1};" : "=l"(d) : "r"(s))
#define CP_ASYNC16(dst, src) \
    asm volatile("cp.async.ca.shared.global [%0], [%1], 16;" :: "r"(dst), "l"(src))
#define CP_COMMIT() asm volatile("cp.async.commit_group;" ::: "memory")
#define CP_WAIT(n)  asm volatile("cp.async.wait_group %0;" :: "n"(n) : "memory")

// monotonic float->uint map (preserves <, including negatives)
__device__ __forceinline__ uint32_t ord_f32(float f) {
    uint32_t u = __float_as_uint(f);
    return (u & 0x80000000u) ? ~u : (u | 0x80000000u);
}

// ---------------- prep: transpose codebook + norms --------------------------
__global__ void __launch_bounds__(NTHREADS)
prep_cb(const float* __restrict__ cb) {
    int k = blockIdx.x * blockDim.x + threadIdx.x;
    if (k >= KTOT) return;
    float s = 0.f;
#pragma unroll
    for (int d4 = 0; d4 < DD; d4 += 4) {
        float4 v = *(const float4*)(cb + (size_t)k * DD + d4);
        s += v.x * v.x + v.y * v.y + v.z * v.z + v.w * v.w;
        g_cbT[(d4 + 0) * KTOT + k] = v.x;
        g_cbT[(d4 + 1) * KTOT + k] = v.y;
        g_cbT[(d4 + 2) * KTOT + k] = v.z;
        g_cbT[(d4 + 3) * KTOT + k] = v.w;
    }
    g_cnorm[k] = s;
}

// ---------------- main fused kernel -----------------------------------------
__global__ void __launch_bounds__(NTHREADS, 2)
vq_kernel(const float* __restrict__ x, const float* __restrict__ cb,
          float* __restrict__ out, int write_idx) {
    extern __shared__ float smem[];
    float* ps  = smem;                       // [DD][PSROW]  ps[d][p]
    float* cs0 = smem + DD * PSROW;          // [DD][CSROW]  buffer 0
    float* cs1 = cs0 + DD * CSROW;           // [DD][CSROW]  buffer 1

    const int tid = threadIdx.x;
    const int wid = tid >> 5;          // warp -> codewords 16*wid..16*wid+15
    const int tx  = tid & 31;          // lane -> points 4*tx..4*tx+3

    const int bh0 = blockIdx.x * 2;    // two (b,h) rows per block
    const int b  = bh0 >> 6;
    const int h0 = bh0 & 63;
    const float* xbase = x + (size_t)b * (DD * 4096) + (size_t)h0 * 64;

    uint32_t sbase;
    asm("{ .reg .u64 t; cvta.to.shared.u64 t, %1; cvt.u32.u64 %0, t; }"
        : "=r"(sbase) : "l"(smem));
    const uint32_t cs_u32[2] = {sbase + (uint32_t)(DD * PSROW) * 4u,
                                sbase + (uint32_t)(DD * PSROW + DD * CSROW) * 4u};
    float* const cs_ptr[2] = {cs0, cs1};

    const int ld_d0 = tid >> 5;        // cp.async: d = ld_d0 + 8r
    const int ld_c4 = (tid & 31) * 4;  // cp.async: codeword quad

    // Point tile: ps[d][p], p = r*64 + w (2 h-rows). Natural float4 copy.
    for (int i = tid; i < DD * 32; i += NTHREADS) {
        int d  = i >> 5;
        int p4 = (i & 31) * 4;         // 0..124
        *(float4*)(ps + d * PSROW + p4) =
            *(const float4*)(xbase + (size_t)d * 4096 + (p4 >> 6) * 64 + (p4 & 63));
    }

    // Prefetch chunk 0 into buffer 0.
#pragma unroll
    for (int r = 0; r < 8; r++) {
        int d = ld_d0 + 8 * r;
        CP_ASYNC16(cs_u32[0] + (uint32_t)(d * CSROW + ld_c4) * 4u,
                   g_cbT + (size_t)d * KTOT + ld_c4);
    }
    CP_COMMIT();

    // Per-lane best for its 4 points: packed (ordered_d2 << 32) | codeword.
    unsigned long long best[4];
#pragma unroll
    for (int p = 0; p < 4; p++) best[p] = 0xFFFFFFFFFFFFFFFFull;

    for (int j = 0; j < NCHUNK; j++) {
        const int buf = j & 1;
        if (j + 1 < NCHUNK) {
            const int chunk1 = (j + 1) * TK;
#pragma unroll
            for (int r = 0; r < 8; r++) {
                int d = ld_d0 + 8 * r;
                CP_ASYNC16(cs_u32[buf ^ 1] + (uint32_t)(d * CSROW + ld_c4) * 4u,
                           g_cbT + (size_t)d * KTOT + chunk1 + ld_c4);
            }
            CP_COMMIT();
            CP_WAIT(1);
        } else {
            CP_WAIT(0);
        }
        __syncthreads();

        const float* csw = cs_ptr[buf] + 16 * wid;   // warp's 16 codewords
        const float* psl = ps + 4 * tx;              // lane's 4 points

        // acc[p][q]: point p (4), codeword pair q (8) -> cw 16*wid+2q, +2q+1
        unsigned long long acc[4][8];
#pragma unroll
        for (int p = 0; p < 4; p++)
#pragma unroll
            for (int q = 0; q < 8; q++) acc[p][q] = 0ull;

#pragma unroll 4
        for (int d = 0; d < DD; d++) {
            // lane's 4 points at this d: 1 distributed LDS.128
            float4 pv = *(const float4*)(psl + (size_t)d * PSROW);
            unsigned long long a0, a1, a2, a3;
            DUP2(a0, __float_as_uint(pv.x));
            DUP2(a1, __float_as_uint(pv.y));
            DUP2(a2, __float_as_uint(pv.z));
            DUP2(a3, __float_as_uint(pv.w));
            // warp's 16 codewords at this d: 4 broadcast LDS.128, pairs native
            const ulonglong2* cr = (const ulonglong2*)(csw + (size_t)d * CSROW);
            ulonglong2 c01 = cr[0];   // pairs q=0,1
            ulonglong2 c23 = cr[1];   // pairs q=2,3
            ulonglong2 c45 = cr[2];   // pairs q=4,5
            ulonglong2 c67 = cr[3];   // pairs q=6,7
            FMA2(acc[0][0], a0, c01.x); FMA2(acc[0][1], a0, c01.y);
            FMA2(acc[0][2], a0, c23.x); FMA2(acc[0][3], a0, c23.y);
            FMA2(acc[0][4], a0, c45.x); FMA2(acc[0][5], a0, c45.y);
            FMA2(acc[0][6], a0, c67.x); FMA2(acc[0][7], a0, c67.y);
            FMA2(acc[1][0], a1, c01.x); FMA2(acc[1][1], a1, c01.y);
            FMA2(acc[1][2], a1, c23.x); FMA2(acc[1][3], a1, c23.y);
            FMA2(acc[1][4], a1, c45.x); FMA2(acc[1][5], a1, c45.y);
            FMA2(acc[1][6], a1, c67.x); FMA2(acc[1][7], a1, c67.y);
            FMA2(acc[2][0], a2, c01.x); FMA2(acc[2][1], a2, c01.y);
            FMA2(acc[2][2], a2, c23.x); FMA2(acc[2][3], a2, c23.y);
            FMA2(acc[2][4], a2, c45.x); FMA2(acc[2][5], a2, c45.y);
            FMA2(acc[2][6], a2, c67.x); FMA2(acc[2][7], a2, c67.y);
            FMA2(acc[3][0], a3, c01.x); FMA2(acc[3][1], a3, c01.y);
            FMA2(acc[3][2], a3, c23.x); FMA2(acc[3][3], a3, c23.y);
            FMA2(acc[3][4], a3, c45.x); FMA2(acc[3][5], a3, c45.y);
            FMA2(acc[3][6], a3, c67.x); FMA2(acc[3][7], a3, c67.y);
        }

        // d2 = ||c||^2 - 2 x.c ; ascending cw order; packed u64 min keeps
        // the smallest index on ties (first occurrence, like jnp.argmin).
        const int cw0 = j * TK + 16 * wid;
#pragma unroll
        for (int q = 0; q < 8; q++) {
            float2 nrm = __ldg((const float2*)(g_cnorm + cw0 + 2 * q));
#pragma unroll
            for (int p = 0; p < 4; p++) {
                uint32_t u0, u1;
                UNPACK2(u0, u1, acc[p][q]);
                float d2a = fmaf(-2.f, __uint_as_float(u0), nrm.x);
                float d2b = fmaf(-2.f, __uint_as_float(u1), nrm.y);
                unsigned long long ca =
                    ((unsigned long long)ord_f32(d2a) << 32) | (unsigned)(cw0 + 2 * q);
                unsigned long long cb2 =
                    ((unsigned long long)ord_f32(d2b) << 32) | (unsigned)(cw0 + 2 * q + 1);
                if (ca  < best[p]) best[p] = ca;
                if (cb2 < best[p]) best[p] = cb2;
            }
        }
        __syncthreads();   // all warps done with cs[buf] before refill
    }

    // Merge across the 8 warps (each covered a disjoint codeword subset).
    unsigned long long* mb = (unsigned long long*)smem;  // [PTS][8], 8 KB (ps dead)
#pragma unroll
    for (int p = 0; p < 4; p++) mb[(4 * tx + p) * 8 + wid] = best[p];
    __syncthreads();

    int* bidx = (int*)(smem + 2048);   // 128 ints
    if (tid < PTS) {
        unsigned long long m = mb[tid * 8];
#pragma unroll
        for (int wsrc = 1; wsrc < 8; wsrc++) {
            unsigned long long v = mb[tid * 8 + wsrc];
            if (v < m) m = v;
        }
        bidx[tid] = (int)(m & 0xFFFFFFFFull);
    }
    __syncthreads();

    // Gather winning codebook rows coalesced into smem, then write transposed.
    float* tmp = smem + 2304;  // [PTS][68] staging = 8704 floats (fits in ps area)
    for (int i = tid; i < PTS * 16; i += NTHREADS) {
        int p  = i >> 4;
        int d4 = (i & 15) * 4;
        *(float4*)(tmp + p * 68 + d4) =
            *(const float4*)(cb + (size_t)bidx[p] * DD + d4);
    }
    __syncthreads();
    float* qbase = out + (size_t)b * (DD * 4096) + (size_t)h0 * 64;
    for (int i = tid; i < DD * 32; i += NTHREADS) {
        int d  = i >> 5;
        int p4 = (i & 31) * 4;
        float4 v;
        v.x = tmp[(p4 + 0) * 68 + d];
        v.y = tmp[(p4 + 1) * 68 + d];
        v.z = tmp[(p4 + 2) * 68 + d];
        v.w = tmp[(p4 + 3) * 68 + d];
        *(float4*)(qbase + (size_t)d * 4096 + (p4 >> 6) * 64 + (p4 & 63)) = v;
    }

    if (write_idx && tid < PTS) {
        out[(size_t)4194304 + (size_t)bh0 * 64 + tid] = (float)bidx[tid];
    }
}

// ---------------- launch -----------------------------------------------------
extern "C" void kernel_launch(void* const* d_in, const int* in_sizes, int n_in,
                              void* d_out, int out_size) {
    const float* x  = (const float*)d_in[0];
    const float* cb = (const float*)d_in[1];
    if (n_in >= 2 && in_sizes[0] == KTOT * DD && in_sizes[1] == 16 * 64 * 64 * 64) {
        x  = (const float*)d_in[1];
        cb = (const float*)d_in[0];
    }
    float* out = (float*)d_out;

    const int smem_bytes = SMEM_FLOATS * (int)sizeof(float);
    cudaFuncSetAttribute(vq_kernel, cudaFuncAttributeMaxDynamicSharedMemorySize,
                         smem_bytes);

    int write_idx = (out_size >= 4194304 + 65536) ? 1 : 0;
    prep_cb<<<(KTOT + NTHREADS - 1) / NTHREADS, NTHREADS>>>(cb);
    vq_kernel<<<512, NTHREADS, smem_bytes>>>(x, cb, out, write_idx);
}